// round 5
// baseline (speedup 1.0000x reference)
#include <cuda_runtime.h>
#include <cuda_bf16.h>
#include <cstdint>

// Problem constants (fixed shapes from reference setup_inputs)
#define N 384
#define D 512
#define MARGIN 1.0f

// Scratch: device globals (no allocation allowed)
__device__ float g_G[N * N];        // Gram matrix X @ X^T (fp32)
__device__ float g_sq[N];           // fp32 row sums of x*x
__device__ float g_asum[N];         // per-anchor triplet loss sum
__device__ int   g_acnt[N];         // per-anchor valid-triple count

// ---------------------------------------------------------------------------
// Kernel 0: fp32 squared row norms (one block per row, deterministic order)
// ---------------------------------------------------------------------------
__global__ void sumsq_kernel(const float* __restrict__ X) {
    const int row = blockIdx.x;
    const int tid = threadIdx.x;     // 128 threads
    __shared__ float red[128];

    const float* xr = X + row * D;
    float s = 0.0f;
#pragma unroll
    for (int i = 0; i < D / 128; i++) {
        float v = xr[tid + i * 128];
        s = fmaf(v, v, s);
    }
    red[tid] = s;
    __syncthreads();
#pragma unroll
    for (int st = 64; st > 0; st >>= 1) {
        if (tid < st) red[tid] += red[tid + st];
        __syncthreads();
    }
    if (tid == 0) g_sq[row] = red[0];
}

// ---------------------------------------------------------------------------
// Kernel 1: G = X @ X^T, 32x32 tiles, fp32 accumulation.
// Grid (12,12), block (32,8); each thread computes 4 outputs.
// ---------------------------------------------------------------------------
__global__ void gram_kernel(const float* __restrict__ X) {
    __shared__ float As[32][33];
    __shared__ float Bs[32][33];

    const int tx = threadIdx.x;          // 0..31
    const int ty = threadIdx.y;          // 0..7
    const int row0 = blockIdx.y * 32;
    const int col0 = blockIdx.x * 32;

    float acc0 = 0.f, acc1 = 0.f, acc2 = 0.f, acc3 = 0.f;

    for (int k0 = 0; k0 < D; k0 += 32) {
#pragma unroll
        for (int i = 0; i < 4; i++) {
            int r = ty + i * 8;
            As[r][tx] = X[(row0 + r) * D + k0 + tx];
            Bs[r][tx] = X[(col0 + r) * D + k0 + tx];
        }
        __syncthreads();
#pragma unroll
        for (int k = 0; k < 32; k++) {
            float b = Bs[tx][k];
            acc0 = fmaf(As[ty +  0][k], b, acc0);
            acc1 = fmaf(As[ty +  8][k], b, acc1);
            acc2 = fmaf(As[ty + 16][k], b, acc2);
            acc3 = fmaf(As[ty + 24][k], b, acc3);
        }
        __syncthreads();
    }

    g_G[(row0 + ty +  0) * N + col0 + tx] = acc0;
    g_G[(row0 + ty +  8) * N + col0 + tx] = acc1;
    g_G[(row0 + ty + 16) * N + col0 + tx] = acc2;
    g_G[(row0 + ty + 24) * N + col0 + tx] = acc3;
}

// ---------------------------------------------------------------------------
// Kernel 2: one block per anchor a.  Labels are INT32 (JAX x64 is disabled,
// so the reference's "int64" labels are silently int32).
//  - distance row: d = sqrt(max(sq[a]+sq[b]-2*G[a,b], 0))
//  - deterministic ballot compaction into pos/neg distance lists
//  - parallel pair sum of relu(dp - dn + margin)
//  - deterministic shared-memory tree reduction -> g_asum[a], g_acnt[a]
// ---------------------------------------------------------------------------
__global__ void triplet_kernel(const int* __restrict__ labels) {
    const int a = blockIdx.x;
    const int tid = threadIdx.x;         // 256 threads

    __shared__ float dr[N];
    __shared__ float pd[N];
    __shared__ float nd[N];
    __shared__ int   s_np, s_nn;
    __shared__ float red[256];

    const float sqa = g_sq[a];
    const int la = labels[a];

    // distance row
    for (int b = tid; b < N; b += 256) {
        float d2 = sqa + g_sq[b] - 2.0f * g_G[a * N + b];
        d2 = fmaxf(d2, 0.0f);
        dr[b] = sqrtf(d2);
    }
    __syncthreads();

    // warp 0: deterministic (index-ordered) compaction
    if (tid < 32) {
        int npos = 0, nneg = 0;
#pragma unroll
        for (int c = 0; c < N / 32; c++) {
            int b = c * 32 + tid;
            bool isp = (labels[b] == la);
            unsigned m = __ballot_sync(0xffffffffu, isp);
            int below_pos = __popc(m & ((1u << tid) - 1u));
            float d = dr[b];
            if (isp) pd[npos + below_pos] = d;
            else     nd[nneg + (tid - below_pos)] = d;
            int p = __popc(m);
            npos += p;
            nneg += 32 - p;
        }
        if (tid == 0) { s_np = npos; s_nn = nneg; }
    }
    __syncthreads();

    const int np = s_np;
    const int nn = s_nn;
    const int total = np * nn;

    float acc = 0.0f;
    for (int i = tid; i < total; i += 256) {
        int p = i / nn;
        int n = i - p * nn;
        acc += fmaxf(pd[p] - nd[n] + MARGIN, 0.0f);
    }
    red[tid] = acc;
    __syncthreads();

#pragma unroll
    for (int s = 128; s > 0; s >>= 1) {
        if (tid < s) red[tid] += red[tid + s];
        __syncthreads();
    }

    if (tid == 0) {
        g_asum[a] = red[0];
        g_acnt[a] = total;
    }
}

// ---------------------------------------------------------------------------
// Kernel 3: deterministic reduction of per-anchor partials + final divide.
// ---------------------------------------------------------------------------
__global__ void finalize_kernel(float* __restrict__ out) {
    const int tid = threadIdx.x;         // 128 threads
    __shared__ float rs[128];
    __shared__ int   rc[128];

    float s = 0.0f;
    int   c = 0;
    for (int i = tid; i < N; i += 128) {
        s += g_asum[i];
        c += g_acnt[i];
    }
    rs[tid] = s;
    rc[tid] = c;
    __syncthreads();

#pragma unroll
    for (int st = 64; st > 0; st >>= 1) {
        if (tid < st) { rs[tid] += rs[tid + st]; rc[tid] += rc[tid + st]; }
        __syncthreads();
    }

    if (tid == 0) {
        out[0] = rs[0] / ((float)rc[0] + 1e-16f);
    }
}

// ---------------------------------------------------------------------------
extern "C" void kernel_launch(void* const* d_in, const int* in_sizes, int n_in,
                              void* d_out, int out_size) {
    const float* X      = (const float*)d_in[0];
    const int*   labels = (const int*)d_in[1];
    float*       out    = (float*)d_out;

    sumsq_kernel<<<N, 128>>>(X);
    dim3 gb(N / 32, N / 32);
    dim3 tb(32, 8);
    gram_kernel<<<gb, tb>>>(X);
    triplet_kernel<<<N, 256>>>(labels);
    finalize_kernel<<<1, 128>>>(out);
}